// round 16
// baseline (speedup 1.0000x reference)
#include <cuda_runtime.h>
#include <cuda_fp16.h>
#include <mma.h>
#include <cstdint>

using namespace nvcuda;

#define BB 2
#define CC 128
#define NN 10000
#define KK 16

// ---- gemm config (round-12 body): TMG=80, exact tiling, 57KB smem ----
#define TMG 80
#define NTG (NN / TMG)               // 125 exactly
#define GT 320                       // 10 warps
#define LDN 88
#define LDW 136
#define LDD 140
#define XH_BYTES (CC * LDN * 2)          // 22528
#define WS_BYTES (CC * LDW * 2)          // 34816
#define DYN_SMEM (XH_BYTES + WS_BYTES)   // 57344 (>= D phase 80*140*4=44800)

// ---- gat config: 128-thr blocks -> 16 CTAs/SM = 64 warps (100% occ) ----
#define GNPB 8                        // nodes per gat block
#define GATT 128

// Scratch
__device__ __align__(16) __half g_whh[BB * NN * CC];  // [b][n][c] fp16
__device__ float g_s1[BB * NN];
__device__ float g_s2[BB * NN];

extern __shared__ char dyn_smem[];

// ---------------------------------------------------------------------------
// Kernel 1: WMMA GEMM fp16/fp32, tile 80n x 128o, K=128 (round-12 proven body)
// ---------------------------------------------------------------------------
__global__ void __launch_bounds__(GT) gemm_wmma(const float* __restrict__ x,
                                                const float* __restrict__ W,
                                                const float* __restrict__ a) {
    __shared__ float a_s[2 * CC];
    __shared__ float s_part[4][2][TMG];

    half*  xh = (half*)dyn_smem;                 // [CC][LDN]
    half*  ws = (half*)(dyn_smem + XH_BYTES);    // [CC][LDW] as ws[o][c]
    float* D  = (float*)dyn_smem;                // phase 2: [TMG][LDD]

    int tid = threadIdx.x;
    int b = blockIdx.y;
    int n0 = blockIdx.x * TMG;

    if (tid < 2 * CC) a_s[tid] = a[tid];

    // Stage x tile (5120 float2, 16/thread, full unroll, exact tiling)
#pragma unroll
    for (int it = 0; it < 16; it++) {
        int idx = it * GT + tid;
        int c = idx / 40;
        int n2 = idx - c * 40;
        float2 xv = *(const float2*)&x[((size_t)b * CC + c) * NN + n0 + n2 * 2];
        *(half2*)&xh[c * LDN + n2 * 2] = __floats2half2_rn(xv.x, xv.y);
    }
    // Stage W (8192 float2, 26 guarded iters)
#pragma unroll
    for (int it = 0; it < 26; it++) {
        int idx = it * GT + tid;
        if (idx < 8192) {
            int o = idx >> 6;
            int c2 = idx & 63;
            float2 wv = *(const float2*)&W[o * CC + c2 * 2];
            *(half2*)&ws[o * LDW + c2 * 2] = __floats2half2_rn(wv.x, wv.y);
        }
    }
    __syncthreads();

    int w = tid >> 5;
    int ni = w >> 1;   // 0..4 -> nodes [ni*16, +16)
    int oi = w & 1;    // 0..1 -> o [oi*64, +64)

    wmma::fragment<wmma::accumulator, 16, 16, 16, float> acc[4];
#pragma unroll
    for (int j = 0; j < 4; j++) wmma::fill_fragment(acc[j], 0.f);

#pragma unroll
    for (int k = 0; k < 8; k++) {
        wmma::fragment<wmma::matrix_a, 16, 16, 16, half, wmma::col_major> af;
        wmma::load_matrix_sync(af, xh + (k * 16) * LDN + ni * 16, LDN);
#pragma unroll
        for (int j = 0; j < 4; j++) {
            wmma::fragment<wmma::matrix_b, 16, 16, 16, half, wmma::col_major> bf;
            wmma::load_matrix_sync(bf, ws + (oi * 64 + j * 16) * LDW + k * 16, LDW);
            wmma::mma_sync(acc[j], af, bf, acc[j]);
        }
    }
    __syncthreads();

#pragma unroll
    for (int j = 0; j < 4; j++)
        wmma::store_matrix_sync(D + (ni * 16) * LDD + oi * 64 + j * 16,
                                acc[j], LDD, wmma::mem_row_major);
    __syncthreads();

    // Epilogue: 320 thr = 80 nodes x 4 o-quarters
    {
        int hf = tid / TMG;
        int nd = tid - hf * TMG;
        int n = n0 + nd;
        const float* row = D + nd * LDD + hf * 32;
        float s1 = 0.f, s2 = 0.f;
        half2 hrow[16];
#pragma unroll
        for (int q = 0; q < 8; q++) {
            float4 v = *(const float4*)&row[q * 4];
            int o = hf * 32 + q * 4;
            s1 += a_s[o] * v.x + a_s[o + 1] * v.y + a_s[o + 2] * v.z + a_s[o + 3] * v.w;
            s2 += a_s[CC + o] * v.x + a_s[CC + o + 1] * v.y
                + a_s[CC + o + 2] * v.z + a_s[CC + o + 3] * v.w;
            hrow[q * 2]     = __floats2half2_rn(v.x, v.y);
            hrow[q * 2 + 1] = __floats2half2_rn(v.z, v.w);
        }
        s_part[hf][0][nd] = s1;
        s_part[hf][1][nd] = s2;
        uint4* dst = (uint4*)&g_whh[((size_t)b * NN + n) * CC + hf * 32];
#pragma unroll
        for (int q = 0; q < 4; q++) dst[q] = ((uint4*)hrow)[q];
    }
    __syncthreads();

    if (tid < 2 * TMG) {
        int which = tid / TMG;
        int nd = tid - which * TMG;
        float s = s_part[0][which][nd] + s_part[1][which][nd]
                + s_part[2][which][nd] + s_part[3][which][nd];
        if (which) g_s2[b * NN + n0 + nd] = s;
        else       g_s1[b * NN + n0 + nd] = s;
    }
}

// ---------------------------------------------------------------------------
// Kernel 2: attention + aggregation. Round-8 warp body, but 128-thr blocks
// (8 nodes, 4 warps, 4.2KB smem) with launch_bounds(128,16): 16 CTAs/SM =
// 64 warps = 100% occupancy (was 51 warps / 78%).
// ---------------------------------------------------------------------------
__global__ void __launch_bounds__(GATT, 16) gat_kernel(const int* __restrict__ ei,
                                                       float* __restrict__ out) {
    __shared__ float hs[GNPB * 132];

    int tid = threadIdx.x;   // 128
    int lane = tid & 31;
    int w = tid >> 5;        // 0..3
    int b = blockIdx.y;
    int n0 = blockIdx.x * GNPB;        // grid.x = 1250
    int nh = lane >> 4;
    int nl = 2 * w + nh;               // 0..7
    int n = n0 + nl;
    int kk = lane & 15;

    int j = ei[(((size_t)0 * BB + b) * NN + n) * KK + kk];
    int i = ei[(((size_t)1 * BB + b) * NN + n) * KK + kk];

    float e = g_s1[b * NN + i] + g_s2[b * NN + j];
    e = (e > 0.f) ? e : 0.2f * e;

    // softmax within each 16-lane half
    float em = e;
#pragma unroll
    for (int m = 8; m; m >>= 1) em = fmaxf(em, __shfl_xor_sync(0xffffffffu, em, m));
    float p = __expf(e - em);
    float ps = p;
#pragma unroll
    for (int m = 8; m; m >>= 1) ps += __shfl_xor_sync(0xffffffffu, ps, m);
    float A = p / ps;

    const uint4* whb = (const uint4*)g_whh + (size_t)b * NN * 16;
    int hbase = lane & 16;
    float acc[8];
#pragma unroll
    for (int q = 0; q < 8; q++) acc[q] = 0.f;

#pragma unroll
    for (int batch = 0; batch < 4; batch++) {
        uint4 v[4];
#pragma unroll
        for (int t = 0; t < 4; t++) {
            int jk = __shfl_sync(0xffffffffu, j, hbase + batch * 4 + t);
            v[t] = whb[(size_t)jk * 16 + kk];
        }
#pragma unroll
        for (int t = 0; t < 4; t++) {
            float Ak = __shfl_sync(0xffffffffu, A, hbase + batch * 4 + t);
            const __half2* h = (const __half2*)&v[t];
#pragma unroll
            for (int q = 0; q < 4; q++) {
                float2 f = __half22float2(h[q]);
                acc[2 * q]     += Ak * f.x;
                acc[2 * q + 1] += Ak * f.y;
            }
        }
    }

    *(float4*)&hs[nl * 132 + kk * 8]     = *(float4*)&acc[0];
    *(float4*)&hs[nl * 132 + kk * 8 + 4] = *(float4*)&acc[4];
    __syncthreads();

    // transposed coalesced write: 128c x 8n = 1024 floats, 8 iters exact
#pragma unroll
    for (int r = 0; r < 8; r++) {
        int idx = r * GATT + tid;
        int c = idx >> 3;          // /GNPB
        int nn = idx & 7;
        out[((size_t)b * CC + c) * NN + n0 + nn] = hs[nn * 132 + c];
    }
}

// ---------------------------------------------------------------------------
extern "C" void kernel_launch(void* const* d_in, const int* in_sizes, int n_in,
                              void* d_out, int out_size) {
    const float* x = (const float*)d_in[0];       // [B,C,N,1]
    const int* ei  = (const int*)d_in[1];         // [2,B,N,K]
    const float* W = (const float*)d_in[2];       // [C,C]
    const float* a = (const float*)d_in[3];       // [2C]
    float* out     = (float*)d_out;               // [B,C,N,1]

    cudaFuncSetAttribute(gemm_wmma, cudaFuncAttributeMaxDynamicSharedMemorySize,
                         DYN_SMEM);
    gemm_wmma<<<dim3(NTG, BB), GT, DYN_SMEM>>>(x, W, a);
    gat_kernel<<<dim3(NN / GNPB, BB), GATT>>>(ei, out);
}